// round 15
// baseline (speedup 1.0000x reference)
#include <cuda_runtime.h>
#include <cuda_fp16.h>
#include <cstdint>

#define N_ROWS 8192
#define K_DIM  512
#define J_DIM  256
#define KI     16          // k-iterations (32 k each)

// ---------------- smem layout (bytes) ----------------
#define B_ST      40960
#define ARAW_OFF  81920
#define ARAW_ST   28672
#define ACV_OFF   139264
#define ACV_ST    35840
#define SMEM_SIZE 210944
#define EPI_STRIDE 132
#define EPI_MAT    59136

// ---------------- device scratch ----------------
__device__ __half g_B[2][2][J_DIM][K_DIM];   // [mat][hi/lo][n][k]
__device__ float  g_part[2][N_ROWS];
__device__ int    g_done1;                    // prep-complete counter
__device__ int    g_done2;                    // exit counter (for reset)

// ---------------- helpers ----------------
__device__ __forceinline__ uint32_t smem_u32(const void* p) {
    uint32_t a;
    asm("{ .reg .u64 t; cvta.to.shared.u64 t, %1; cvt.u32.u64 %0, t; }" : "=r"(a) : "l"(p));
    return a;
}
__device__ __forceinline__ void cp16(uint32_t sdst, const void* g) {
    asm volatile("cp.async.cg.shared.global [%0], [%1], 16;" :: "r"(sdst), "l"(g));
}
__device__ __forceinline__ void cp_commit() { asm volatile("cp.async.commit_group;"); }
template <int N>
__device__ __forceinline__ void cp_wait() { asm volatile("cp.async.wait_group %0;" :: "n"(N)); }

__device__ __forceinline__ void ldsm4(uint32_t (&r)[4], uint32_t addr) {
    asm volatile("ldmatrix.sync.aligned.m8n8.x4.shared.b16 {%0,%1,%2,%3}, [%4];"
        : "=r"(r[0]), "=r"(r[1]), "=r"(r[2]), "=r"(r[3]) : "r"(addr));
}
__device__ __forceinline__ void mma16816(float (&c)[4], const uint32_t (&a)[4],
                                         uint32_t b0, uint32_t b1) {
    asm volatile("mma.sync.aligned.m16n8k16.row.col.f32.f16.f16.f32 "
        "{%0,%1,%2,%3}, {%4,%5,%6,%7}, {%8,%9}, {%0,%1,%2,%3};"
        : "+f"(c[0]), "+f"(c[1]), "+f"(c[2]), "+f"(c[3])
        : "r"(a[0]), "r"(a[1]), "r"(a[2]), "r"(a[3]), "r"(b0), "r"(b1));
}
__device__ __forceinline__ uint32_t packh2(__half a, __half b) {
    __half2 h = __halves2half2(a, b);
    return *reinterpret_cast<uint32_t*>(&h);
}
__device__ __forceinline__ void split(float x, __half& hi, __half& lo) {
    hi = __float2half_rn(x);
    lo = __float2half_rn(x - __half2float(hi));
}

// ============ GEMM: 148 persistent CTAs, in-kernel W prep, K-outer ============
__global__ void __launch_bounds__(256, 1)
gemm_kernel(const float* __restrict__ user, const float* __restrict__ event,
            const float* __restrict__ Wu, const float* __restrict__ We,
            const float* __restrict__ bu, const float* __restrict__ be)
{
    extern __shared__ __align__(1024) char smem[];
    const uint32_t sb = smem_u32(smem);
    const int tid  = threadIdx.x;
    const int wid  = tid >> 5;
    const int lane = tid & 31;

    const int ntile = (blockIdx.x >= 74) ? 1 : 0;
    const int b     = blockIdx.x - ntile * 74;
    const int r0    = (b < 68) ? 7 * b : 476 + 6 * (b - 68);
    const int TC    = (b < 68) ? 7 : 6;
    const int n0    = ntile * 128;
    const int row_base = r0 * 16;

    const char* bflat = reinterpret_cast<const char*>(&g_B[0][0][0][0]);

    auto issue_B = [&](int t, int st) {
        #pragma unroll
        for (int i = 0; i < 8; ++i) {
            const int c = tid + i * 256;
            const int nrow = c >> 2, q = c & 3;
            const int m = nrow >> 8, h = (nrow >> 7) & 1, n = nrow & 127;
            cp16(sb + st * B_ST + nrow * 80 + q * 16,
                 bflat + ((size_t)((m * 2 + h) * J_DIM + n0 + n)) * (K_DIM * 2)
                       + (size_t)t * 64 + q * 16);
        }
    };
    auto issue_A = [&](int t, int st) {
        #pragma unroll
        for (int i = 0; i < 7; ++i) {
            const int e = tid + i * 256;
            const int m = (e >= 896) ? 1 : 0;
            const int rem = e - m * 896;
            const int row = rem >> 3, q = rem & 7;
            int rg = row_base + row;
            if (rg > N_ROWS - 1) rg = N_ROWS - 1;
            cp16(sb + ARAW_OFF + st * ARAW_ST + m * 14336 + row * 128 + q * 16,
                 (m ? event : user) + (size_t)rg * K_DIM + t * 32 + q * 4);
        }
    };
    auto convert = [&](int t) {
        const int st = t & 1;
        #pragma unroll
        for (int i = 0; i < 7; ++i) {
            const int e = tid + i * 256;
            const int m = (e >= 896) ? 1 : 0;
            const int rem = e - m * 896;
            const int row = rem >> 3, q = rem & 7;
            const float4 v = *reinterpret_cast<const float4*>(
                smem + ARAW_OFF + st * ARAW_ST + m * 14336 + row * 128 + q * 16);
            __half hx, lx, hy, ly, hz, lz, hw, lw;
            split(v.x, hx, lx); split(v.y, hy, ly);
            split(v.z, hz, lz); split(v.w, hw, lw);
            const int tile = row >> 4, lr = row & 15;
            const uint32_t base = ACV_OFF + st * ACV_ST + m * 17920
                                + tile * 1280 + lr * 80 + q * 8;
            *reinterpret_cast<uint2*>(smem + base) =
                make_uint2(packh2(hx, hy), packh2(hz, hw));
            *reinterpret_cast<uint2*>(smem + base + 8960) =
                make_uint2(packh2(lx, ly), packh2(lz, lw));
        }
    };

    const int g    = wid >> 2;
    const int colq = wid & 3;
    const uint32_t a_lane = (uint32_t)((lane & 15) * 80 + (lane >> 4) * 16);
    const uint32_t b_lane = (uint32_t)(((lane & 7) + ((lane >> 4) & 1) * 8 + colq * 32) * 80
                                       + ((lane >> 3) & 1) * 16);

    float acc[7][4][4];
    #pragma unroll
    for (int j = 0; j < 7; ++j)
        #pragma unroll
        for (int no = 0; no < 4; ++no)
            #pragma unroll
            for (int x = 0; x < 4; ++x) acc[j][no][x] = 0.f;

    // ---- prologue phase 1: A(0) (no W dependency) ----
    issue_A(0, 0); cp_commit();

    // ---- in-kernel W prep: 65536 items over 37888 threads (2 apiece) ----
    // item = m(1) | kq(7) | n(8), n fastest -> coalesced LDG
    {
        const int base_i = blockIdx.x * 256 + tid;          // 0..37887
        #pragma unroll
        for (int it = 0; it < 2; ++it) {
            const int idx = base_i + it * 37888;
            if (idx < 65536) {
                const int m  = idx >> 15;
                const int kq = (idx >> 8) & 127;
                const int n  = idx & 255;
                const float* W = m ? We : Wu;
                __half h0, l0, h1, l1, h2, l2, h3, l3;
                split(W[(size_t)(4 * kq + 0) * J_DIM + n], h0, l0);
                split(W[(size_t)(4 * kq + 1) * J_DIM + n], h1, l1);
                split(W[(size_t)(4 * kq + 2) * J_DIM + n], h2, l2);
                split(W[(size_t)(4 * kq + 3) * J_DIM + n], h3, l3);
                *reinterpret_cast<uint2*>(&g_B[m][0][n][4 * kq]) =
                    make_uint2(packh2(h0, h1), packh2(h2, h3));
                *reinterpret_cast<uint2*>(&g_B[m][1][n][4 * kq]) =
                    make_uint2(packh2(l0, l1), packh2(l2, l3));
            }
        }
        __threadfence();
        __syncthreads();
        if (tid == 0) {
            atomicAdd(&g_done1, 1);
            while (*(volatile int*)&g_done1 < 148) { }
            const int o = atomicAdd(&g_done2, 1);
            if (o == 147) {          // last CTA through: reset for next replay
                g_done1 = 0;
                __threadfence();
                g_done2 = 0;
            }
        }
        __syncthreads();             // all threads wait for flag before B reads
    }

    // ---- prologue phase 2 ----
    issue_B(0, 0); issue_A(1, 1); cp_commit();
    cp_wait<1>();
    __syncthreads();
    convert(0);
    __syncthreads();
    issue_B(1, 1); issue_A(2, 0); cp_commit();

    // ---- main loop ----
    for (int t = 0; t < KI; ++t) {
        const int st = t & 1;
        if (t < KI - 1) cp_wait<1>(); else cp_wait<0>();
        __syncthreads();

        const uint32_t aH = sb + ACV_OFF + st * ACV_ST + g * 17920 + a_lane;
        const uint32_t aL = aH + 8960;
        const uint32_t bH = sb + st * B_ST + g * 20480 + b_lane;
        const uint32_t bL = bH + 10240;
        #pragma unroll
        for (int ks = 0; ks < 2; ++ks) {
            const uint32_t kb = ks * 32;
            uint32_t bh[2][4], bl[2][4];
            ldsm4(bh[0], bH + kb);
            ldsm4(bh[1], bH + 1280 + kb);
            ldsm4(bl[0], bL + kb);
            ldsm4(bl[1], bL + 1280 + kb);
            #pragma unroll
            for (int j = 0; j < 7; ++j) {
                uint32_t ah[4], al[4];
                ldsm4(ah, aH + j * 1280 + kb);
                ldsm4(al, aL + j * 1280 + kb);
                mma16816(acc[j][0], ah, bh[0][0], bh[0][1]);
                mma16816(acc[j][1], ah, bh[0][2], bh[0][3]);
                mma16816(acc[j][2], ah, bh[1][0], bh[1][1]);
                mma16816(acc[j][3], ah, bh[1][2], bh[1][3]);
                mma16816(acc[j][0], ah, bl[0][0], bl[0][1]);
                mma16816(acc[j][1], ah, bl[0][2], bl[0][3]);
                mma16816(acc[j][2], ah, bl[1][0], bl[1][1]);
                mma16816(acc[j][3], ah, bl[1][2], bl[1][3]);
                mma16816(acc[j][0], al, bh[0][0], bh[0][1]);
                mma16816(acc[j][1], al, bh[0][2], bh[0][3]);
                mma16816(acc[j][2], al, bh[1][0], bh[1][1]);
                mma16816(acc[j][3], al, bh[1][2], bh[1][3]);
            }
        }

        if (t + 1 < KI) convert(t + 1);
        __syncthreads();

        if (t + 2 < KI) {
            issue_B(t + 2, t & 1);
            if (t + 3 < KI) issue_A(t + 3, (t + 1) & 1);
            cp_commit();
        }
    }

    // ---- epilogue: stage tiles, partial dot -> g_part ----
    __syncthreads();
    float* ep = reinterpret_cast<float*>(smem + g * EPI_MAT);
    #pragma unroll
    for (int j = 0; j < 7; ++j) {
        if (j < TC) {
            #pragma unroll
            for (int no = 0; no < 4; ++no) {
                const int row = j * 16 + (lane >> 2);
                const int col = colq * 32 + no * 8 + (lane & 3) * 2;
                *reinterpret_cast<float2*>(&ep[row * EPI_STRIDE + col]) =
                    make_float2(acc[j][no][0], acc[j][no][1]);
                *reinterpret_cast<float2*>(&ep[(row + 8) * EPI_STRIDE + col]) =
                    make_float2(acc[j][no][2], acc[j][no][3]);
            }
        }
    }
    __syncthreads();

    const int nrows = TC * 16;
    if (tid < nrows) {
        const float* Us = reinterpret_cast<const float*>(smem);
        const float* Es = reinterpret_cast<const float*>(smem + EPI_MAT);
        float ssum = 0.f;
        #pragma unroll
        for (int cb = 0; cb < 32; ++cb) {
            const int col = cb * 4;
            const float4 u  = *reinterpret_cast<const float4*>(&Us[tid * EPI_STRIDE + col]);
            const float4 e  = *reinterpret_cast<const float4*>(&Es[tid * EPI_STRIDE + col]);
            const float4 b1 = *reinterpret_cast<const float4*>(&bu[n0 + col]);
            const float4 b2 = *reinterpret_cast<const float4*>(&be[n0 + col]);
            ssum += (u.x + b1.x) * (e.x + b2.x)
                  + (u.y + b1.y) * (e.y + b2.y)
                  + (u.z + b1.z) * (e.z + b2.z)
                  + (u.w + b1.w) * (e.w + b2.w);
        }
        g_part[ntile][row_base + tid] = ssum;
    }
}

// ============ combine ============
__global__ void __launch_bounds__(256)
combine_kernel(float* __restrict__ out)
{
    const int i = blockIdx.x * 256 + threadIdx.x;
    const float l = g_part[0][i] + g_part[1][i];
    out[i] = 1.0f / (1.0f + expf(-l));
}

extern "C" void kernel_launch(void* const* d_in, const int* in_sizes, int n_in,
                              void* d_out, int out_size)
{
    const float* user  = (const float*)d_in[0];
    const float* event = (const float*)d_in[1];
    const float* Wu    = (const float*)d_in[2];
    const float* bu    = (const float*)d_in[3];
    const float* We    = (const float*)d_in[4];
    const float* be    = (const float*)d_in[5];
    float* out = (float*)d_out;

    cudaFuncSetAttribute(gemm_kernel, cudaFuncAttributeMaxDynamicSharedMemorySize, SMEM_SIZE);

    gemm_kernel<<<148, 256, SMEM_SIZE>>>(user, event, Wu, We, bu, be);
    combine_kernel<<<N_ROWS / 256, 256>>>(out);
}

// round 17
// speedup vs baseline: 1.0444x; 1.0444x over previous
#include <cuda_runtime.h>
#include <cuda_fp16.h>
#include <cstdint>

#define N_ROWS 8192
#define K_DIM  512
#define J_DIM  256
#define KI     16          // k-iterations (32 k each)

// ---------------- smem layout (bytes) ----------------
// ARAW: 2 stages x [m][112 rows][128B]   = 2 x 28672 @ 0
// ACNV: 2 stages x [m][h][7][16][80B]    = 2 x 35840 @ 57344
// BCNV: 2 stages x [m*2+h][128 n][80B]   = 2 x 40960 @ 129024
#define ARAW_OFF  0
#define ARAW_ST   28672
#define ACV_OFF   57344
#define ACV_ST    35840
#define BCNV_OFF  129024
#define BCNV_ST   40960
#define SMEM_SIZE 210944
// epilogue staging (reuse whole region @0): [m][112 rows][132 floats]
#define EPI_STRIDE 132
#define EPI_MAT    59136

// ---------------- device scratch ----------------
__device__ float g_part[2][N_ROWS];

// ---------------- helpers ----------------
__device__ __forceinline__ uint32_t smem_u32(const void* p) {
    uint32_t a;
    asm("{ .reg .u64 t; cvta.to.shared.u64 t, %1; cvt.u32.u64 %0, t; }" : "=r"(a) : "l"(p));
    return a;
}
__device__ __forceinline__ void cp16(uint32_t sdst, const void* g) {
    asm volatile("cp.async.cg.shared.global [%0], [%1], 16;" :: "r"(sdst), "l"(g));
}
__device__ __forceinline__ void cp_commit() { asm volatile("cp.async.commit_group;"); }
template <int N>
__device__ __forceinline__ void cp_wait() { asm volatile("cp.async.wait_group %0;" :: "n"(N)); }

__device__ __forceinline__ void ldsm4(uint32_t (&r)[4], uint32_t addr) {
    asm volatile("ldmatrix.sync.aligned.m8n8.x4.shared.b16 {%0,%1,%2,%3}, [%4];"
        : "=r"(r[0]), "=r"(r[1]), "=r"(r[2]), "=r"(r[3]) : "r"(addr));
}
__device__ __forceinline__ void mma16816(float (&c)[4], const uint32_t (&a)[4],
                                         uint32_t b0, uint32_t b1) {
    asm volatile("mma.sync.aligned.m16n8k16.row.col.f32.f16.f16.f32 "
        "{%0,%1,%2,%3}, {%4,%5,%6,%7}, {%8,%9}, {%0,%1,%2,%3};"
        : "+f"(c[0]), "+f"(c[1]), "+f"(c[2]), "+f"(c[3])
        : "r"(a[0]), "r"(a[1]), "r"(a[2]), "r"(a[3]), "r"(b0), "r"(b1));
}
__device__ __forceinline__ uint32_t packh2(__half a, __half b) {
    __half2 h = __halves2half2(a, b);
    return *reinterpret_cast<uint32_t*>(&h);
}
__device__ __forceinline__ void split(float x, __half& hi, __half& lo) {
    hi = __float2half_rn(x);
    lo = __float2half_rn(x - __half2float(hi));
}

// ============ GEMM: 148 persistent CTAs, in-loop W convert (no prep kernel) ============
__global__ void __launch_bounds__(256, 1)
gemm_kernel(const float* __restrict__ user, const float* __restrict__ event,
            const float* __restrict__ Wu, const float* __restrict__ We,
            const float* __restrict__ bu, const float* __restrict__ be)
{
    extern __shared__ __align__(1024) char smem[];
    const uint32_t sb = smem_u32(smem);
    const int tid  = threadIdx.x;
    const int wid  = tid >> 5;
    const int lane = tid & 31;

    const int ntile = (blockIdx.x >= 74) ? 1 : 0;
    const int b     = blockIdx.x - ntile * 74;
    const int r0    = (b < 68) ? 7 * b : 476 + 6 * (b - 68);
    const int TC    = (b < 68) ? 7 : 6;
    const int n0    = ntile * 128;
    const int row_base = r0 * 16;

    // ---- A copy (cp.async, double-buffered raw) ----
    auto issue_A = [&](int t, int st) {
        #pragma unroll
        for (int i = 0; i < 7; ++i) {
            const int e = tid + i * 256;               // 1792 chunks
            const int m = (e >= 896) ? 1 : 0;
            const int rem = e - m * 896;
            const int row = rem >> 3, q = rem & 7;
            int rg = row_base + row;
            if (rg > N_ROWS - 1) rg = N_ROWS - 1;
            cp16(sb + ARAW_OFF + st * ARAW_ST + m * 14336 + row * 128 + q * 16,
                 (m ? event : user) + (size_t)rg * K_DIM + t * 32 + q * 4);
        }
    };

    // ---- convert: A raw(st) -> ACNV(st), W gmem -> BCNV(st) ----
    auto convert = [&](int t) {
        const int st = t & 1;
        // A: 1792 float4 items
        #pragma unroll
        for (int i = 0; i < 7; ++i) {
            const int e = tid + i * 256;
            const int m = (e >= 896) ? 1 : 0;
            const int rem = e - m * 896;
            const int row = rem >> 3, q = rem & 7;
            const float4 v = *reinterpret_cast<const float4*>(
                smem + ARAW_OFF + st * ARAW_ST + m * 14336 + row * 128 + q * 16);
            __half hx, lx, hy, ly, hz, lz, hw, lw;
            split(v.x, hx, lx); split(v.y, hy, ly);
            split(v.z, hz, lz); split(v.w, hw, lw);
            const int tile = row >> 4, lr = row & 15;
            const uint32_t base = ACV_OFF + st * ACV_ST + m * 17920
                                + tile * 1280 + lr * 80 + q * 8;
            *reinterpret_cast<uint2*>(smem + base) =
                make_uint2(packh2(hx, hy), packh2(hz, hw));
            *reinterpret_cast<uint2*>(smem + base + 8960) =
                make_uint2(packh2(lx, ly), packh2(lz, lw));
        }
        // B: 2048 items (m, kq, n); LDG straight from W (L2-resident, coalesced over n)
        #pragma unroll
        for (int i = 0; i < 8; ++i) {
            const int c = tid + i * 256;
            const int m = c >> 10, rem = c & 1023, kq = rem >> 7, n = rem & 127;
            const float* W = (m ? We : Wu) + (size_t)(t * 32 + kq * 4) * J_DIM + n0 + n;
            __half h0, l0, h1, l1, h2, l2, h3, l3;
            split(W[0 * J_DIM], h0, l0);
            split(W[1 * J_DIM], h1, l1);
            split(W[2 * J_DIM], h2, l2);
            split(W[3 * J_DIM], h3, l3);
            const uint32_t cb = BCNV_OFF + st * BCNV_ST + m * 20480 + n * 80 + kq * 8;
            *reinterpret_cast<uint2*>(smem + cb) =
                make_uint2(packh2(h0, h1), packh2(h2, h3));
            *reinterpret_cast<uint2*>(smem + cb + 10240) =
                make_uint2(packh2(l0, l1), packh2(l2, l3));
        }
    };

    const int g    = wid >> 2;
    const int colq = wid & 3;
    const uint32_t a_lane = (uint32_t)((lane & 15) * 80 + (lane >> 4) * 16);
    const uint32_t b_lane = (uint32_t)(((lane & 7) + ((lane >> 4) & 1) * 8 + colq * 32) * 80
                                       + ((lane >> 3) & 1) * 16);

    float acc[7][4][4];
    #pragma unroll
    for (int j = 0; j < 7; ++j)
        #pragma unroll
        for (int no = 0; no < 4; ++no)
            #pragma unroll
            for (int x = 0; x < 4; ++x) acc[j][no][x] = 0.f;

    // ---- prologue ----
    issue_A(0, 0); cp_commit();
    issue_A(1, 1); cp_commit();
    cp_wait<1>();                  // raw(0) done
    __syncthreads();
    convert(0);
    __syncthreads();

    // ---- main loop ----
    for (int t = 0; t < KI; ++t) {
        const int st = t & 1;

        // compute(t) from conv stage st (MMAs drain async)
        const uint32_t aH = sb + ACV_OFF + st * ACV_ST + g * 17920 + a_lane;
        const uint32_t aL = aH + 8960;
        const uint32_t bH = sb + BCNV_OFF + st * BCNV_ST + g * 20480 + b_lane;
        const uint32_t bL = bH + 10240;
        #pragma unroll
        for (int ks = 0; ks < 2; ++ks) {
            const uint32_t kb = ks * 32;
            uint32_t bh[2][4], bl[2][4];
            ldsm4(bh[0], bH + kb);
            ldsm4(bh[1], bH + 1280 + kb);
            ldsm4(bl[0], bL + kb);
            ldsm4(bl[1], bL + 1280 + kb);
            #pragma unroll
            for (int j = 0; j < 7; ++j) {
                uint32_t ah[4], al[4];
                ldsm4(ah, aH + j * 1280 + kb);
                ldsm4(al, aL + j * 1280 + kb);
                mma16816(acc[j][0], ah, bh[0][0], bh[0][1]);
                mma16816(acc[j][1], ah, bh[0][2], bh[0][3]);
                mma16816(acc[j][2], ah, bh[1][0], bh[1][1]);
                mma16816(acc[j][3], ah, bh[1][2], bh[1][3]);
                mma16816(acc[j][0], ah, bl[0][0], bl[0][1]);
                mma16816(acc[j][1], ah, bl[0][2], bl[0][3]);
                mma16816(acc[j][2], ah, bl[1][0], bl[1][1]);
                mma16816(acc[j][3], ah, bl[1][2], bl[1][3]);
                mma16816(acc[j][0], al, bh[0][0], bh[0][1]);
                mma16816(acc[j][1], al, bh[0][2], bh[0][3]);
                mma16816(acc[j][2], al, bh[1][0], bh[1][1]);
                mma16816(acc[j][3], al, bh[1][2], bh[1][3]);
            }
        }

        // shadow phase: wait raw(t+1), issue raw(t+2), convert(t+1)
        if (t + 1 < KI) {
            cp_wait<0>();          // only raw(t+1) outstanding here
            __syncthreads();       // all threads' raw(t+1) visible; compute(t) lds done
            if (t + 2 < KI) { issue_A(t + 2, st); cp_commit(); }  // raw(st) freed by convert(t)
            convert(t + 1);        // writes conv st^1 (freed by compute(t-1))
        }
        __syncthreads();
    }

    // ---- epilogue: stage tiles (reuse all smem), partial dot -> g_part ----
    float* ep = reinterpret_cast<float*>(smem + g * EPI_MAT);
    #pragma unroll
    for (int j = 0; j < 7; ++j) {
        if (j < TC) {
            #pragma unroll
            for (int no = 0; no < 4; ++no) {
                const int row = j * 16 + (lane >> 2);
                const int col = colq * 32 + no * 8 + (lane & 3) * 2;
                *reinterpret_cast<float2*>(&ep[row * EPI_STRIDE + col]) =
                    make_float2(acc[j][no][0], acc[j][no][1]);
                *reinterpret_cast<float2*>(&ep[(row + 8) * EPI_STRIDE + col]) =
                    make_float2(acc[j][no][2], acc[j][no][3]);
            }
        }
    }
    __syncthreads();

    const int nrows = TC * 16;
    if (tid < nrows) {
        const float* Us = reinterpret_cast<const float*>(smem);
        const float* Es = reinterpret_cast<const float*>(smem + EPI_MAT);
        float ssum = 0.f;
        #pragma unroll
        for (int cb = 0; cb < 32; ++cb) {
            const int col = cb * 4;
            const float4 u  = *reinterpret_cast<const float4*>(&Us[tid * EPI_STRIDE + col]);
            const float4 e  = *reinterpret_cast<const float4*>(&Es[tid * EPI_STRIDE + col]);
            const float4 b1 = *reinterpret_cast<const float4*>(&bu[n0 + col]);
            const float4 b2 = *reinterpret_cast<const float4*>(&be[n0 + col]);
            ssum += (u.x + b1.x) * (e.x + b2.x)
                  + (u.y + b1.y) * (e.y + b2.y)
                  + (u.z + b1.z) * (e.z + b2.z)
                  + (u.w + b1.w) * (e.w + b2.w);
        }
        g_part[ntile][row_base + tid] = ssum;
    }
}

// ============ combine ============
__global__ void __launch_bounds__(256)
combine_kernel(float* __restrict__ out)
{
    const int i = blockIdx.x * 256 + threadIdx.x;
    const float l = g_part[0][i] + g_part[1][i];
    out[i] = 1.0f / (1.0f + expf(-l));
}

extern "C" void kernel_launch(void* const* d_in, const int* in_sizes, int n_in,
                              void* d_out, int out_size)
{
    const float* user  = (const float*)d_in[0];
    const float* event = (const float*)d_in[1];
    const float* Wu    = (const float*)d_in[2];
    const float* bu    = (const float*)d_in[3];
    const float* We    = (const float*)d_in[4];
    const float* be    = (const float*)d_in[5];
    float* out = (float*)d_out;

    cudaFuncSetAttribute(gemm_kernel, cudaFuncAttributeMaxDynamicSharedMemorySize, SMEM_SIZE);

    gemm_kernel<<<148, 256, SMEM_SIZE>>>(user, event, Wu, We, bu, be);
    combine_kernel<<<N_ROWS / 256, 256>>>(out);
}